// round 2
// baseline (speedup 1.0000x reference)
#include <cuda_runtime.h>

// Sizes: x (256,4096) f32, weights (64,64,64) f32, out (256,4096) f32.
// out[b, f*64+n] = sum_c sum_m w[f,c,m] * x[b, c*64 + (n-m) mod 64]
// computed in the 64-point DFT domain with rfft symmetry (33 freqs).

#define NF 33
#define BSZ 256
#define CC 64
#define FF 64

// [k][row] planes. Wf rows = f*64+c (4096), Xf rows = b*64+c (16384),
// S rows = b*64+f (16384).
__device__ float2 g_Wf[NF * FF * CC];
__device__ float2 g_Xf[NF * BSZ * CC];
__device__ float2 g_S [NF * BSZ * FF];

// ---------------------------------------------------------------------------
// Kernel 1: forward DFT of every length-64 row of w (4096 rows) and x (16384
// rows). One warp per row; lane = frequency k (0..31) via phasor recurrence,
// k=32 via a signed warp reduction. Stores k-planes (strided across lanes).
// ---------------------------------------------------------------------------
__global__ void __launch_bounds__(256) k_dft(const float* __restrict__ x,
                                             const float* __restrict__ w) {
    __shared__ float rowbuf[8][64];
    const int warp = threadIdx.x >> 5;
    const int lane = threadIdx.x & 31;
    const int row  = blockIdx.x * 8 + warp;   // 0..20479

    const float* src;
    float2* dst;
    int plane;
    if (row < FF * CC) {            // weight rows first
        src = w + row * 64;
        dst = g_Wf + row;
        plane = FF * CC;
    } else {
        int r = row - FF * CC;
        src = x + r * 64;
        dst = g_Xf + r;
        plane = BSZ * CC;
    }

    const float v0 = src[lane];
    const float v1 = src[lane + 32];
    rowbuf[warp][lane]      = v0;
    rowbuf[warp][lane + 32] = v1;
    __syncwarp();

    // twiddle step e^{-2*pi*i*k/64}, k = lane
    float s, c;
    sincospif(-(float)lane * (1.0f / 32.0f), &s, &c);
    float tr = 1.0f, ti = 0.0f;
    float ar = 0.0f, ai = 0.0f;
#pragma unroll
    for (int j = 0; j < 64; j++) {
        const float v = rowbuf[warp][j];
        ar = fmaf(v, tr, ar);
        ai = fmaf(v, ti, ai);
        const float nr = fmaf(tr, c, -ti * s);
        ti = fmaf(tr, s, ti * c);
        tr = nr;
    }
    dst[lane * plane] = make_float2(ar, ai);

    // k = 32: sum (-1)^j row[j]  (real)
    float p = v0 + v1;
    if (lane & 1) p = -p;
#pragma unroll
    for (int o = 16; o; o >>= 1) p += __shfl_xor_sync(0xffffffffu, p, o);
    if (lane == 0) dst[32 * plane] = make_float2(p, 0.0f);
}

// ---------------------------------------------------------------------------
// Kernel 2: per-frequency complex GEMM. Grid (4 b-tiles, 33 freqs), 256 thr.
// Tile: 64b x 64f, reduction over 64 c. 4x4 register blocking per thread.
// Xs reads are 2-way broadcasts (conflict-free); Ws padded to pitch 65 so
// the 16 strided f-reads fan across all 32 banks.
// ---------------------------------------------------------------------------
__global__ void __launch_bounds__(256) k_gemm() {
    extern __shared__ float2 sm[];
    float2* Xs = sm;            // [64][64]   (b-major, pitch 64)
    float2* Ws = sm + 64 * 64;  // [64][65]   (f-major, pitch 65)

    const int k  = blockIdx.y;
    const int b0 = blockIdx.x * 64;
    const float2* gX = g_Xf + k * (BSZ * CC) + b0 * CC;
    const float2* gW = g_Wf + k * (FF * CC);

#pragma unroll
    for (int i = threadIdx.x; i < 4096; i += 256) {
        Xs[i] = gX[i];
        Ws[(i >> 6) * 65 + (i & 63)] = gW[i];
    }
    __syncthreads();

    const int tf = threadIdx.x & 15;
    const int tb = threadIdx.x >> 4;

    float Sr[4][4] = {}, Si[4][4] = {};
#pragma unroll 4
    for (int c = 0; c < 64; c++) {
        float2 xv[4], wv[4];
#pragma unroll
        for (int j = 0; j < 4; j++) xv[j] = Xs[(tb + 16 * j) * 64 + c];
#pragma unroll
        for (int i = 0; i < 4; i++) wv[i] = Ws[(tf + 16 * i) * 65 + c];
#pragma unroll
        for (int j = 0; j < 4; j++)
#pragma unroll
            for (int i = 0; i < 4; i++) {
                Sr[j][i] = fmaf(xv[j].x, wv[i].x, Sr[j][i]);
                Sr[j][i] = fmaf(-xv[j].y, wv[i].y, Sr[j][i]);
                Si[j][i] = fmaf(xv[j].x, wv[i].y, Si[j][i]);
                Si[j][i] = fmaf(xv[j].y, wv[i].x, Si[j][i]);
            }
    }

    float2* gS = g_S + k * (BSZ * FF) + b0 * FF;
#pragma unroll
    for (int j = 0; j < 4; j++)
#pragma unroll
        for (int i = 0; i < 4; i++)
            gS[(tb + 16 * j) * FF + (tf + 16 * i)] =
                make_float2(Sr[j][i], Si[j][i]);
}

// ---------------------------------------------------------------------------
// Kernel 3: real inverse transform as a tiny GEMM against a constant 33x64
// (complex) matrix built from a 64-entry twiddle table.
//   out[r][n] = sum_k Sr[k][r]*Br[k][n] + Si[k][r]*Bi[k][n]
//   Br[k][n] = s_k * cos(2*pi*k*n/64), Bi[k][n] = -s_k * sin(2*pi*k*n/64)
//   s_k = 1/64 for k in {0,32}, else 2/64.
// 512 CTAs x 256 thr; CTA handles 32 rows, thread = (row, 8-wide n group).
// ---------------------------------------------------------------------------
__global__ void __launch_bounds__(256) k_inv(float* __restrict__ out) {
    __shared__ float2 Ssh[32][NF];   // [row][k]
    __shared__ float2 Bm[NF][64];    // (Br, Bi) interleaved
    __shared__ float2 tw[64];

    const int t = threadIdx.x;
    if (t < 64) {
        float s, c;
        sincospif((float)t * (1.0f / 32.0f), &s, &c);
        tw[t] = make_float2(c, s);
    }
    __syncthreads();
    for (int i = t; i < NF * 64; i += 256) {
        const int k = i >> 6, n = i & 63;
        const float sc = (k == 0 || k == 32) ? (1.0f / 64.0f) : (2.0f / 64.0f);
        const float2 wv = tw[(k * n) & 63];
        Bm[k][n] = make_float2(sc * wv.x, -sc * wv.y);
    }

    const int r0 = blockIdx.x * 32;
    for (int i = t; i < 32 * NF; i += 256) {
        const int rl = i & 31, k = i >> 5;
        Ssh[rl][k] = g_S[k * (BSZ * FF) + r0 + rl];
    }
    __syncthreads();

    const int ng  = t & 7;    // n-group: n = ng*8 .. ng*8+7
    const int row = t >> 3;   // 0..31

    float acc[8] = {0, 0, 0, 0, 0, 0, 0, 0};
    for (int k = 0; k < NF; k++) {
        const float2 sv = Ssh[row][k];
#pragma unroll
        for (int u = 0; u < 8; u++) {
            const float2 b = Bm[k][ng * 8 + u];
            acc[u] = fmaf(sv.x, b.x, acc[u]);
            acc[u] = fmaf(sv.y, b.y, acc[u]);
        }
    }

    float4* o = (float4*)(out + (r0 + row) * 64 + ng * 8);
    o[0] = make_float4(acc[0], acc[1], acc[2], acc[3]);
    o[1] = make_float4(acc[4], acc[5], acc[6], acc[7]);
}

// ---------------------------------------------------------------------------
extern "C" void kernel_launch(void* const* d_in, const int* in_sizes, int n_in,
                              void* d_out, int out_size) {
    const float* x = (const float*)d_in[0];
    const float* w = (const float*)d_in[1];
    // Defensive: identify by element count (x = 1048576, w = 262144).
    if (n_in >= 2 && in_sizes[0] == 64 * 64 * 64) {
        x = (const float*)d_in[1];
        w = (const float*)d_in[0];
    }

    static const size_t gemm_smem = (64 * 64 + 64 * 65) * sizeof(float2); // 66048
    cudaFuncSetAttribute(k_gemm, cudaFuncAttributeMaxDynamicSharedMemorySize,
                         (int)gemm_smem);

    // 20480 rows total (4096 weight rows + 16384 x rows), 8 rows per CTA.
    k_dft<<<2560, 256>>>(x, w);
    k_gemm<<<dim3(4, 33), 256, gemm_smem>>>();
    k_inv<<<512, 256>>>((float*)d_out);
}